// round 1
// baseline (speedup 1.0000x reference)
#include <cuda_runtime.h>
#include <cstdint>

#define N      4096
#define D      64
#define NB     128      // persistent-kernel block count (<= 148 SMs => all co-resident)
#define ITERS  100

// ---------------- device globals (scratch; no allocation allowed) ----------------
__device__ float    g_K[(size_t)N * N];   // 64 MB  K = exp(-M/eps)
__device__ float    g_M[(size_t)N * N];   // 64 MB  squared distances (clamped >= 0)
__device__ float    g_sq0[N];
__device__ float    g_sq1[N];
__device__ float    g_u[N];
__device__ float    g_v[N];
__device__ unsigned g_arrive;             // grid barrier counter (monotone per launch)
__device__ int      g_changed[ITERS];     // per-iteration change flags
__device__ float    g_cost;

// ---------------- init: reset all cross-launch state -----------------------------
__global__ void kern_init() {
    int t = threadIdx.x;
    if (t == 0) { g_arrive = 0u; g_cost = 0.0f; }
    if (t < ITERS) g_changed[t] = 0;
}

// ---------------- row squared norms ----------------------------------------------
__global__ void kern_norms(const float* __restrict__ x0, const float* __restrict__ x1) {
    int i = blockIdx.x * blockDim.x + threadIdx.x;   // 0 .. 2N-1
    if (i >= 2 * N) return;
    const float* p = (i < N) ? (x0 + (size_t)i * D) : (x1 + (size_t)(i - N) * D);
    const float4* p4 = (const float4*)p;
    float s = 0.0f;
#pragma unroll
    for (int k = 0; k < D / 4; k++) {
        float4 q = p4[k];
        s += q.x * q.x + q.y * q.y + q.z * q.z + q.w * q.w;
    }
    if (i < N) g_sq0[i] = s; else g_sq1[i - N] = s;
}

// ---------------- K / M build: 128x128 tile fp32 GEMM + exp with underflow skip --
__global__ void __launch_bounds__(256) kern_K(const float* __restrict__ x0,
                                              const float* __restrict__ x1) {
    __shared__ float As[32][128];   // x0 tile, k-major
    __shared__ float Bs[32][128];   // x1 tile, k-major
    const int tid = threadIdx.x;
    const int tx = tid & 15;        // 0..15 -> 8 cols each
    const int ty = tid >> 4;        // 0..15 -> 8 rows each
    const int row0 = blockIdx.y * 128;
    const int col0 = blockIdx.x * 128;

    float acc[8][8];
#pragma unroll
    for (int i = 0; i < 8; i++)
#pragma unroll
        for (int j = 0; j < 8; j++) acc[i][j] = 0.0f;

    for (int kc = 0; kc < D; kc += 32) {
        // Load 128 rows x 32 k of each operand (1024 float4 total; 4 per thread)
#pragma unroll
        for (int i = 0; i < 4; i++) {
            int f  = tid + i * 256;      // 0..1023
            int r  = f >> 3;             // local row (8 float4 per 32-float row)
            int c4 = f & 7;
            float4 a = *(const float4*)(x0 + (size_t)(row0 + r) * D + kc + c4 * 4);
            As[c4 * 4 + 0][r] = a.x; As[c4 * 4 + 1][r] = a.y;
            As[c4 * 4 + 2][r] = a.z; As[c4 * 4 + 3][r] = a.w;
            float4 b = *(const float4*)(x1 + (size_t)(col0 + r) * D + kc + c4 * 4);
            Bs[c4 * 4 + 0][r] = b.x; Bs[c4 * 4 + 1][r] = b.y;
            Bs[c4 * 4 + 2][r] = b.z; Bs[c4 * 4 + 3][r] = b.w;
        }
        __syncthreads();
#pragma unroll
        for (int k = 0; k < 32; k++) {
            float a8[8], b8[8];
            *(float4*)&a8[0] = *(const float4*)&As[k][ty * 8];
            *(float4*)&a8[4] = *(const float4*)&As[k][ty * 8 + 4];
            *(float4*)&b8[0] = *(const float4*)&Bs[k][tx * 8];
            *(float4*)&b8[4] = *(const float4*)&Bs[k][tx * 8 + 4];
#pragma unroll
            for (int i = 0; i < 8; i++)
#pragma unroll
                for (int j = 0; j < 8; j++) acc[i][j] = fmaf(a8[i], b8[j], acc[i][j]);
        }
        __syncthreads();
    }

    // Epilogue: M = max(sq0+sq1-2*dot, 0); K = exp2(M * -log2(e)/eps) with
    // warp-uniform skip when the whole warp underflows (avoids all MUFU work).
    const float LINV = -14.426950408889634f;  // -log2(e)/0.1
#pragma unroll
    for (int ii = 0; ii < 8; ii++) {
        int r = row0 + ty * 8 + ii;
        float s0 = g_sq0[r];
        float mm[8], kk[8];
#pragma unroll
        for (int jj = 0; jj < 8; jj++) {
            int c = col0 + tx * 8 + jj;
            float m = s0 + g_sq1[c] - 2.0f * acc[ii][jj];
            m = fmaxf(m, 0.0f);
            mm[jj] = m;
            float arg = m * LINV;
            bool need = (arg > -130.0f);   // below this exp2 is (sub)denormal ~ 0
            float kv = 0.0f;
            if (__ballot_sync(0xffffffffu, need)) {
                kv = exp2f(arg);
                if (!need) kv = 0.0f;
            }
            kk[jj] = kv;
        }
        size_t base = (size_t)r * N + col0 + tx * 8;
        *(float4*)(g_M + base)     = make_float4(mm[0], mm[1], mm[2], mm[3]);
        *(float4*)(g_M + base + 4) = make_float4(mm[4], mm[5], mm[6], mm[7]);
        *(float4*)(g_K + base)     = make_float4(kk[0], kk[1], kk[2], kk[3]);
        *(float4*)(g_K + base + 4) = make_float4(kk[4], kk[5], kk[6], kk[7]);
    }
}

// ---------------- software grid barrier (all NB blocks co-resident) --------------
__device__ __forceinline__ void gsync(unsigned* nbar) {
    __syncthreads();
    if (threadIdx.x == 0) {
        __threadfence();                       // release my writes (gpu scope)
        atomicAdd(&g_arrive, 1u);
        unsigned tgt = (*nbar + 1u) * (unsigned)NB;
        while (atomicAdd(&g_arrive, 0u) < tgt) __nanosleep(64);
        __threadfence();                       // acquire; flushes L1 (CCTL.IVALL)
    }
    (*nbar)++;
    __syncthreads();
}

// ---------------- persistent Sinkhorn + cost -------------------------------------
__global__ void __launch_bounds__(256) kern_sinkhorn(float* __restrict__ out) {
    const float AB    = 1.0f / (float)N;  // a_i = b_j = 1/N (exact in fp32)
    const float DELTA = 1e-8f;
    const int tid  = threadIdx.x;
    const int bid  = blockIdx.x;
    const int lane = tid & 31;
    const int w    = tid >> 5;            // warp id 0..7
    unsigned nbar = 0;
    __shared__ float sred[256];

    // init u = v = 1
    int gi = bid * 256 + tid;
    if (gi < N) { g_u[gi] = 1.0f; g_v[gi] = 1.0f; }
    gsync(&nbar);

    for (int it = 0; it < ITERS; it++) {
        // ---- u-pass: u = a / (K @ v + delta); warp-per-row, 4 rows/warp ----
#pragma unroll
        for (int rr = 0; rr < 4; rr++) {
            int r = bid * 32 + w * 4 + rr;
            const float4* kr = (const float4*)(g_K + (size_t)r * N);
            const float4* vv = (const float4*)g_v;
            float s = 0.0f;
            for (int j = lane; j < N / 4; j += 32) {
                float4 kq = kr[j];
                float4 vq = vv[j];
                s += kq.x * vq.x + kq.y * vq.y + kq.z * vq.z + kq.w * vq.w;
            }
#pragma unroll
            for (int o = 16; o; o >>= 1) s += __shfl_xor_sync(0xffffffffu, s, o);
            if (lane == 0) {
                float un = AB / (s + DELTA);
                if (un != g_u[r]) g_changed[it] = 1;
                g_u[r] = un;
            }
        }
        gsync(&nbar);

        // ---- v-pass: v = b / (K^T @ u + delta); 32-col stripe per block ----
        {
            int c = bid * 32 + lane;
            float s = 0.0f;
            int r = w;
#pragma unroll 4
            for (; r < N; r += 8)
                s += g_K[(size_t)r * N + c] * g_u[r];
            sred[tid] = s;
            __syncthreads();
            if (tid < 32) {
                float t = sred[tid];
#pragma unroll
                for (int g = 1; g < 8; g++) t += sred[tid + g * 32];
                float vn = AB / (t + DELTA);
                if (vn != g_v[c]) g_changed[it] = 1;
                g_v[c] = vn;
            }
        }
        gsync(&nbar);

        // Exact fixed point: if nothing changed bitwise, all remaining
        // iterations are identity. Uniform across blocks (read after barrier).
        if (g_changed[it] == 0) break;
    }

    // ---- cost = sum_ij u_i * K_ij * v_j * M_ij -------------------------------
    {
        float wsum = 0.0f;
#pragma unroll
        for (int rr = 0; rr < 4; rr++) {
            int r = bid * 32 + w * 4 + rr;
            const float4* kr = (const float4*)(g_K + (size_t)r * N);
            const float4* mr = (const float4*)(g_M + (size_t)r * N);
            const float4* vv = (const float4*)g_v;
            float s = 0.0f;
            for (int j = lane; j < N / 4; j += 32) {
                float4 kq = kr[j];
                float4 mq = mr[j];
                float4 vq = vv[j];
                s += kq.x * mq.x * vq.x + kq.y * mq.y * vq.y
                   + kq.z * mq.z * vq.z + kq.w * mq.w * vq.w;
            }
#pragma unroll
            for (int o = 16; o; o >>= 1) s += __shfl_xor_sync(0xffffffffu, s, o);
            if (lane == 0) wsum += s * g_u[r];
        }
        if (lane == 0) atomicAdd(&g_cost, wsum);
    }
    gsync(&nbar);
    if (bid == 0 && tid == 0) out[0] = g_cost;
}

// ---------------- launch ----------------------------------------------------------
extern "C" void kernel_launch(void* const* d_in, const int* in_sizes, int n_in,
                              void* d_out, int out_size) {
    const float* x0 = (const float*)d_in[0];
    const float* x1 = (const float*)d_in[1];
    float* out = (float*)d_out;

    kern_init<<<1, 128>>>();
    kern_norms<<<(2 * N + 255) / 256, 256>>>(x0, x1);
    dim3 gk(N / 128, N / 128);
    kern_K<<<gk, 256>>>(x0, x1);
    kern_sinkhorn<<<NB, 256>>>(out);
}

// round 3
// speedup vs baseline: 5.3470x; 5.3470x over previous
#include <cuda_runtime.h>
#include <cuda_bf16.h>
#include <cstdint>

#define N      4096
#define D      64
#define NB     128      // persistent-kernel block count (<= SMs => co-resident)
#define ITERS  100
#define NT     32       // 32x32 grid of 128x128 tiles

// ---------------- device globals (scratch; no allocation allowed) ----------------
__device__ float         g_K[(size_t)N * N];   // written only for nonzero tiles
__device__ float         g_M[(size_t)N * N];   // written only for nonzero tiles
__device__ __nv_bfloat16 g_x0h[N * D];
__device__ __nv_bfloat16 g_x1h[N * D];
__device__ float         g_sq0[N];
__device__ float         g_sq1[N];
__device__ float         g_u[N];
__device__ float         g_v[N];
__device__ unsigned      g_arrive;
__device__ int           g_changed[ITERS];
__device__ float         g_cost;
__device__ int           g_tilemap[NT * NT];   // 1 = tile has some K != 0
__device__ int           g_anyK;

// ---------------- init ------------------------------------------------------------
__global__ void kern_init() {
    int t = blockIdx.x * blockDim.x + threadIdx.x;
    if (t < NT * NT) g_tilemap[t] = 0;
    if (t < ITERS)   g_changed[t] = 0;
    if (t == 0) { g_arrive = 0u; g_cost = 0.0f; g_anyK = 0; }
}

// ---------------- row squared norms + bf16 conversion ------------------------------
__global__ void kern_norms(const float* __restrict__ x0, const float* __restrict__ x1) {
    int i = blockIdx.x * blockDim.x + threadIdx.x;   // 0 .. 2N-1
    if (i >= 2 * N) return;
    const float* p = (i < N) ? (x0 + (size_t)i * D) : (x1 + (size_t)(i - N) * D);
    __nv_bfloat16* h = (i < N) ? (g_x0h + (size_t)i * D) : (g_x1h + (size_t)(i - N) * D);
    float s = 0.0f;
#pragma unroll
    for (int k = 0; k < D; k += 4) {
        float4 q = *(const float4*)(p + k);
        s += q.x * q.x + q.y * q.y + q.z * q.z + q.w * q.w;
        h[k + 0] = __float2bfloat16(q.x);
        h[k + 1] = __float2bfloat16(q.y);
        h[k + 2] = __float2bfloat16(q.z);
        h[k + 3] = __float2bfloat16(q.w);
    }
    if (i < N) g_sq0[i] = s; else g_sq1[i - N] = s;
}

// ---------------- K/M build via mma.sync bf16; stores only for nonzero tiles ------
// Block = 256 threads = 8 warps (2 m-groups x 4 n-groups). Tile 128x128, K=64.
__global__ void __launch_bounds__(256) kern_K() {
    const int tid  = threadIdx.x;
    const int w    = tid >> 5;
    const int lane = tid & 31;
    const int gid  = lane >> 2;     // 0..7
    const int pid  = lane & 3;      // 0..3
    const int wm   = w >> 2;        // 0..1
    const int wn   = w & 3;         // 0..3
    const int R0 = blockIdx.y * 128 + wm * 64;
    const int C0 = blockIdx.x * 128 + wn * 32;

    const uint32_t* A = (const uint32_t*)g_x0h;   // row stride = 32 uint32
    const uint32_t* B = (const uint32_t*)g_x1h;

    float acc[4][4][4];
#pragma unroll
    for (int mi = 0; mi < 4; mi++)
#pragma unroll
        for (int ni = 0; ni < 4; ni++)
#pragma unroll
            for (int f = 0; f < 4; f++) acc[mi][ni][f] = 0.0f;

#pragma unroll
    for (int ks = 0; ks < 4; ks++) {
        const int cidx = (ks * 16 + 2 * pid) >> 1;   // uint32 col index
        uint32_t a[4][4];
#pragma unroll
        for (int mi = 0; mi < 4; mi++) {
            int r = R0 + mi * 16 + gid;
            a[mi][0] = A[(size_t)r * 32 + cidx];
            a[mi][1] = A[(size_t)(r + 8) * 32 + cidx];
            a[mi][2] = A[(size_t)r * 32 + cidx + 4];
            a[mi][3] = A[(size_t)(r + 8) * 32 + cidx + 4];
        }
        uint32_t b[4][2];
#pragma unroll
        for (int ni = 0; ni < 4; ni++) {
            int c = C0 + ni * 8 + gid;
            b[ni][0] = B[(size_t)c * 32 + cidx];
            b[ni][1] = B[(size_t)c * 32 + cidx + 4];
        }
#pragma unroll
        for (int mi = 0; mi < 4; mi++)
#pragma unroll
            for (int ni = 0; ni < 4; ni++)
                asm volatile(
                    "mma.sync.aligned.m16n8k16.row.col.f32.bf16.bf16.f32 "
                    "{%0,%1,%2,%3}, {%4,%5,%6,%7}, {%8,%9}, {%0,%1,%2,%3};"
                    : "+f"(acc[mi][ni][0]), "+f"(acc[mi][ni][1]),
                      "+f"(acc[mi][ni][2]), "+f"(acc[mi][ni][3])
                    : "r"(a[mi][0]), "r"(a[mi][1]), "r"(a[mi][2]), "r"(a[mi][3]),
                      "r"(b[ni][0]), "r"(b[ni][1]));
    }

    // Epilogue: m = max(sq0+sq1-2dot, 0). Tile needs materialization only if
    // some element could have exp(-m/0.1) != 0 in fp32 (m < ~10.4; use 11 margin).
    __shared__ int s_need;
    if (tid == 0) s_need = 0;
    __syncthreads();

    float mv[4][4][4];
    int need = 0;
#pragma unroll
    for (int mi = 0; mi < 4; mi++) {
        float s0a = g_sq0[R0 + mi * 16 + gid];
        float s0b = g_sq0[R0 + mi * 16 + gid + 8];
#pragma unroll
        for (int ni = 0; ni < 4; ni++) {
            int c = C0 + ni * 8 + 2 * pid;
            float s1a = g_sq1[c], s1b = g_sq1[c + 1];
            float m0 = fmaxf(fmaf(-2.0f, acc[mi][ni][0], s0a + s1a), 0.0f);
            float m1 = fmaxf(fmaf(-2.0f, acc[mi][ni][1], s0a + s1b), 0.0f);
            float m2 = fmaxf(fmaf(-2.0f, acc[mi][ni][2], s0b + s1a), 0.0f);
            float m3 = fmaxf(fmaf(-2.0f, acc[mi][ni][3], s0b + s1b), 0.0f);
            mv[mi][ni][0] = m0; mv[mi][ni][1] = m1;
            mv[mi][ni][2] = m2; mv[mi][ni][3] = m3;
            need |= (fminf(fminf(m0, m1), fminf(m2, m3)) < 11.0f) ? 1 : 0;
        }
    }
    unsigned wb = __ballot_sync(0xffffffffu, need);
    if (lane == 0 && wb) s_need = 1;
    __syncthreads();

    if (s_need) {
        if (tid == 0) {
            g_tilemap[blockIdx.y * NT + blockIdx.x] = 1;
            g_anyK = 1;
        }
#pragma unroll
        for (int mi = 0; mi < 4; mi++) {
#pragma unroll
            for (int ni = 0; ni < 4; ni++) {
                int r0 = R0 + mi * 16 + gid;
                int c  = C0 + ni * 8 + 2 * pid;
                float m0 = mv[mi][ni][0], m1 = mv[mi][ni][1];
                float m2 = mv[mi][ni][2], m3 = mv[mi][ni][3];
                *(float2*)(g_M + (size_t)r0 * N + c)       = make_float2(m0, m1);
                *(float2*)(g_M + (size_t)(r0 + 8) * N + c) = make_float2(m2, m3);
                *(float2*)(g_K + (size_t)r0 * N + c)       =
                    make_float2(expf(-10.0f * m0), expf(-10.0f * m1));
                *(float2*)(g_K + (size_t)(r0 + 8) * N + c) =
                    make_float2(expf(-10.0f * m2), expf(-10.0f * m3));
            }
        }
    }
}

// ---------------- software grid barrier -------------------------------------------
__device__ __forceinline__ void gsync(unsigned* nbar) {
    __syncthreads();
    if (threadIdx.x == 0) {
        __threadfence();
        atomicAdd(&g_arrive, 1u);
        unsigned tgt = (*nbar + 1u) * (unsigned)NB;
        while (atomicAdd(&g_arrive, 0u) < tgt) __nanosleep(64);
        __threadfence();
    }
    (*nbar)++;
    __syncthreads();
}

// ---------------- persistent Sinkhorn + cost --------------------------------------
__global__ void __launch_bounds__(256) kern_sinkhorn(float* __restrict__ out) {
    // Exact fast path: if every tile of K is identically zero, then K@v == 0,
    // K^T@u == 0, and every cost term u_i*K_ij*v_j*M_ij == 0 -> cost == 0.
    if (g_anyK == 0) {
        if (blockIdx.x == 0 && threadIdx.x == 0) out[0] = 0.0f;
        return;
    }

    const float AB    = 1.0f / (float)N;
    const float DELTA = 1e-8f;
    const int tid  = threadIdx.x;
    const int bid  = blockIdx.x;
    const int lane = tid & 31;
    const int w    = tid >> 5;
    unsigned nbar = 0;
    __shared__ float sred[256];

    int gi = bid * 256 + tid;
    if (gi < N) { g_u[gi] = 1.0f; g_v[gi] = 1.0f; }
    gsync(&nbar);

    for (int it = 0; it < ITERS; it++) {
        // ---- u-pass: warp-per-row, skip all-zero tiles ----
#pragma unroll
        for (int rr = 0; rr < 4; rr++) {
            int r  = bid * 32 + w * 4 + rr;
            int rt = r >> 7;
            const int* map = g_tilemap + rt * NT;
            const float4* kr = (const float4*)(g_K + (size_t)r * N);
            const float4* vv = (const float4*)g_v;
            float s = 0.0f;
            for (int ct = 0; ct < NT; ct++) {
                if (!map[ct]) continue;
                int j = ct * 32 + lane;   // float4 index within row
                float4 kq = kr[j];
                float4 vq = vv[j];
                s += kq.x * vq.x + kq.y * vq.y + kq.z * vq.z + kq.w * vq.w;
            }
#pragma unroll
            for (int o = 16; o; o >>= 1) s += __shfl_xor_sync(0xffffffffu, s, o);
            if (lane == 0) {
                float un = AB / (s + DELTA);
                if (un != g_u[r]) g_changed[it] = 1;
                g_u[r] = un;
            }
        }
        gsync(&nbar);

        // ---- v-pass: 32-col stripe per block, skip all-zero tiles ----
        {
            int c  = bid * 32 + lane;
            int ct = bid >> 2;
            float s = 0.0f;
            for (int rt = 0; rt < NT; rt++) {
                if (!g_tilemap[rt * NT + ct]) continue;
                int rbase = rt * 128;
#pragma unroll 4
                for (int r = rbase + w; r < rbase + 128; r += 8)
                    s += g_K[(size_t)r * N + c] * g_u[r];
            }
            sred[tid] = s;
            __syncthreads();
            if (tid < 32) {
                float t = sred[tid];
#pragma unroll
                for (int g = 1; g < 8; g++) t += sred[tid + g * 32];
                float vn = AB / (t + DELTA);
                if (vn != g_v[c]) g_changed[it] = 1;
                g_v[c] = vn;
            }
        }
        gsync(&nbar);

        if (g_changed[it] == 0) break;   // exact bitwise fixed point
    }

    // ---- cost = sum_ij u_i * K_ij * v_j * M_ij (zero tiles contribute 0) ----
    {
        float wsum = 0.0f;
#pragma unroll
        for (int rr = 0; rr < 4; rr++) {
            int r  = bid * 32 + w * 4 + rr;
            int rt = r >> 7;
            const int* map = g_tilemap + rt * NT;
            const float4* kr = (const float4*)(g_K + (size_t)r * N);
            const float4* mr = (const float4*)(g_M + (size_t)r * N);
            const float4* vv = (const float4*)g_v;
            float s = 0.0f;
            for (int ct = 0; ct < NT; ct++) {
                if (!map[ct]) continue;
                int j = ct * 32 + lane;
                float4 kq = kr[j];
                float4 mq = mr[j];
                float4 vq = vv[j];
                s += kq.x * mq.x * vq.x + kq.y * mq.y * vq.y
                   + kq.z * mq.z * vq.z + kq.w * mq.w * vq.w;
            }
#pragma unroll
            for (int o = 16; o; o >>= 1) s += __shfl_xor_sync(0xffffffffu, s, o);
            if (lane == 0) wsum += s * g_u[r];
        }
        if (lane == 0) atomicAdd(&g_cost, wsum);
    }
    gsync(&nbar);
    if (bid == 0 && tid == 0) out[0] = g_cost;
}

// ---------------- launch ----------------------------------------------------------
extern "C" void kernel_launch(void* const* d_in, const int* in_sizes, int n_in,
                              void* d_out, int out_size) {
    const float* x0 = (const float*)d_in[0];
    const float* x1 = (const float*)d_in[1];
    float* out = (float*)d_out;

    kern_init<<<1, 1024>>>();
    kern_norms<<<(2 * N + 255) / 256, 256>>>(x0, x1);
    dim3 gk(NT, NT);
    kern_K<<<gk, 256>>>();
    kern_sinkhorn<<<NB, 256>>>(out);
}

// round 5
// speedup vs baseline: 8.1078x; 1.5163x over previous
#include <cuda_runtime.h>
#include <cuda_bf16.h>
#include <cstdint>

#define N      4096
#define D      64
#define NB     128      // persistent-kernel block count (<= SMs => co-resident)
#define ITERS  100
#define NT     32       // 32x32 grid of 128x128 tiles

// ---------------- device globals (scratch; no allocation allowed) ----------------
__device__ float         g_K[(size_t)N * N];   // written only for nonzero tiles
__device__ float         g_M[(size_t)N * N];   // written only for nonzero tiles
__device__ __nv_bfloat16 g_x0h[N * D];
__device__ __nv_bfloat16 g_x1h[N * D];
__device__ float         g_sq0[N];
__device__ float         g_sq1[N];
__device__ float         g_u[N];
__device__ float         g_v[N];
__device__ unsigned      g_arrive;
__device__ int           g_changed[ITERS];
__device__ float         g_cost;
__device__ int           g_tilemap[NT * NT];   // 1 = tile has some K != 0
__device__ int           g_anyK;

// ---------------- fused init + row norms + bf16 convert ---------------------------
// grid = 32 x 256 = 8192 threads = 2N exactly.
__global__ void kern_norms(const float* __restrict__ x0, const float* __restrict__ x1) {
    int i = blockIdx.x * blockDim.x + threadIdx.x;   // 0 .. 2N-1
    // init scatter (no later kernel reads these before next launch boundary)
    if (i < NT * NT) g_tilemap[i] = 0;
    if (i < ITERS)   g_changed[i] = 0;
    if (i == 0) { g_arrive = 0u; g_cost = 0.0f; g_anyK = 0; }

    const float* p = (i < N) ? (x0 + (size_t)i * D) : (x1 + (size_t)(i - N) * D);
    __nv_bfloat16* h = (i < N) ? (g_x0h + (size_t)i * D) : (g_x1h + (size_t)(i - N) * D);
    float s = 0.0f;
#pragma unroll
    for (int k = 0; k < D; k += 4) {
        float4 q = *(const float4*)(p + k);
        s += q.x * q.x + q.y * q.y + q.z * q.z + q.w * q.w;
        h[k + 0] = __float2bfloat16(q.x);
        h[k + 1] = __float2bfloat16(q.y);
        h[k + 2] = __float2bfloat16(q.z);
        h[k + 3] = __float2bfloat16(q.w);
    }
    if (i < N) g_sq0[i] = s; else g_sq1[i - N] = s;
}

// ---------------- K/M build: smem-staged bf16 mma; stores only nonzero tiles ------
// Block = 256 threads = 8 warps (2 m-groups x 4 n-groups). Tile 128x128, K=64.
// smem row stride = 36 uint32 (144 B): bank(r*36+c) = (r*4+c) % 32 -> the warp's
// (gid,pid) lane pattern hits all 32 banks (conflict-free), and 144 % 16 == 0
// keeps uint4 stores aligned.
#define SROW 36
__global__ void __launch_bounds__(256) kern_K() {
    __shared__ uint32_t As[128 * SROW];
    __shared__ uint32_t Bs[128 * SROW];

    const int tid  = threadIdx.x;
    const int w    = tid >> 5;
    const int lane = tid & 31;
    const int gid  = lane >> 2;     // 0..7
    const int pid  = lane & 3;      // 0..3
    const int wm   = w >> 2;        // 0..1
    const int wn   = w & 3;         // 0..3
    const int R0 = blockIdx.y * 128;
    const int C0 = blockIdx.x * 128;

    // ---- coalesced tile loads: 128 rows x 32 uint32, 8 float4 per row ----
    const uint4* GA = (const uint4*)(g_x0h + (size_t)R0 * D);
    const uint4* GB = (const uint4*)(g_x1h + (size_t)C0 * D);
#pragma unroll
    for (int i = 0; i < 4; i++) {
        int f  = tid + i * 256;      // 0..1023
        int r  = f >> 3;             // local row
        int c4 = f & 7;              // float4 within row
        *(uint4*)&As[r * SROW + c4 * 4] = GA[(size_t)r * 8 + c4];
        *(uint4*)&Bs[r * SROW + c4 * 4] = GB[(size_t)r * 8 + c4];
    }
    __syncthreads();

    const int AR = wm * 64;          // warp's local A row base
    const int BR = wn * 32;          // warp's local B row base

    float acc[4][4][4];
#pragma unroll
    for (int mi = 0; mi < 4; mi++)
#pragma unroll
        for (int ni = 0; ni < 4; ni++)
#pragma unroll
            for (int f = 0; f < 4; f++) acc[mi][ni][f] = 0.0f;

#pragma unroll
    for (int ks = 0; ks < 4; ks++) {
        const int cidx = ks * 8 + pid;   // uint32 col (k/2)
        uint32_t a[4][4];
#pragma unroll
        for (int mi = 0; mi < 4; mi++) {
            int r = AR + mi * 16 + gid;
            a[mi][0] = As[r * SROW + cidx];
            a[mi][1] = As[(r + 8) * SROW + cidx];
            a[mi][2] = As[r * SROW + cidx + 4];
            a[mi][3] = As[(r + 8) * SROW + cidx + 4];
        }
        uint32_t b[4][2];
#pragma unroll
        for (int ni = 0; ni < 4; ni++) {
            int c = BR + ni * 8 + gid;
            b[ni][0] = Bs[c * SROW + cidx];
            b[ni][1] = Bs[c * SROW + cidx + 4];
        }
#pragma unroll
        for (int mi = 0; mi < 4; mi++)
#pragma unroll
            for (int ni = 0; ni < 4; ni++)
                asm volatile(
                    "mma.sync.aligned.m16n8k16.row.col.f32.bf16.bf16.f32 "
                    "{%0,%1,%2,%3}, {%4,%5,%6,%7}, {%8,%9}, {%0,%1,%2,%3};"
                    : "+f"(acc[mi][ni][0]), "+f"(acc[mi][ni][1]),
                      "+f"(acc[mi][ni][2]), "+f"(acc[mi][ni][3])
                    : "r"(a[mi][0]), "r"(a[mi][1]), "r"(a[mi][2]), "r"(a[mi][3]),
                      "r"(b[ni][0]), "r"(b[ni][1]));
    }

    // Epilogue: m = max(sq0+sq1-2dot, 0). Tile materialized only if some element
    // could have exp(-m/0.1) != 0 in fp32 (m < ~10.4; margin 11 covers bf16 error).
    __shared__ int s_need;
    if (tid == 0) s_need = 0;
    __syncthreads();

    const int WR0 = R0 + wm * 64;
    const int WC0 = C0 + wn * 32;
    float mv[4][4][4];
    int need = 0;
#pragma unroll
    for (int mi = 0; mi < 4; mi++) {
        float s0a = g_sq0[WR0 + mi * 16 + gid];
        float s0b = g_sq0[WR0 + mi * 16 + gid + 8];
#pragma unroll
        for (int ni = 0; ni < 4; ni++) {
            int c = WC0 + ni * 8 + 2 * pid;
            float s1a = g_sq1[c], s1b = g_sq1[c + 1];
            float m0 = fmaxf(fmaf(-2.0f, acc[mi][ni][0], s0a + s1a), 0.0f);
            float m1 = fmaxf(fmaf(-2.0f, acc[mi][ni][1], s0a + s1b), 0.0f);
            float m2 = fmaxf(fmaf(-2.0f, acc[mi][ni][2], s0b + s1a), 0.0f);
            float m3 = fmaxf(fmaf(-2.0f, acc[mi][ni][3], s0b + s1b), 0.0f);
            mv[mi][ni][0] = m0; mv[mi][ni][1] = m1;
            mv[mi][ni][2] = m2; mv[mi][ni][3] = m3;
            need |= (fminf(fminf(m0, m1), fminf(m2, m3)) < 11.0f) ? 1 : 0;
        }
    }
    unsigned wb = __ballot_sync(0xffffffffu, need);
    if (lane == 0 && wb) s_need = 1;
    __syncthreads();

    if (s_need) {
        if (tid == 0) {
            g_tilemap[blockIdx.y * NT + blockIdx.x] = 1;
            g_anyK = 1;
        }
#pragma unroll
        for (int mi = 0; mi < 4; mi++) {
#pragma unroll
            for (int ni = 0; ni < 4; ni++) {
                int r0 = WR0 + mi * 16 + gid;
                int c  = WC0 + ni * 8 + 2 * pid;
                float m0 = mv[mi][ni][0], m1 = mv[mi][ni][1];
                float m2 = mv[mi][ni][2], m3 = mv[mi][ni][3];
                *(float2*)(g_M + (size_t)r0 * N + c)       = make_float2(m0, m1);
                *(float2*)(g_M + (size_t)(r0 + 8) * N + c) = make_float2(m2, m3);
                *(float2*)(g_K + (size_t)r0 * N + c)       =
                    make_float2(expf(-10.0f * m0), expf(-10.0f * m1));
                *(float2*)(g_K + (size_t)(r0 + 8) * N + c) =
                    make_float2(expf(-10.0f * m2), expf(-10.0f * m3));
            }
        }
    }
}

// ---------------- software grid barrier -------------------------------------------
__device__ __forceinline__ void gsync(unsigned* nbar) {
    __syncthreads();
    if (threadIdx.x == 0) {
        __threadfence();
        atomicAdd(&g_arrive, 1u);
        unsigned tgt = (*nbar + 1u) * (unsigned)NB;
        while (atomicAdd(&g_arrive, 0u) < tgt) __nanosleep(64);
        __threadfence();
    }
    (*nbar)++;
    __syncthreads();
}

// ---------------- persistent Sinkhorn + cost --------------------------------------
__global__ void __launch_bounds__(256) kern_sinkhorn(float* __restrict__ out) {
    // Exact fast path: if every tile of K is identically zero, then K@v == 0,
    // K^T@u == 0, and every cost term u_i*K_ij*v_j*M_ij == 0 -> cost == 0.
    if (g_anyK == 0) {
        if (blockIdx.x == 0 && threadIdx.x == 0) out[0] = 0.0f;
        return;
    }

    const float AB    = 1.0f / (float)N;
    const float DELTA = 1e-8f;
    const int tid  = threadIdx.x;
    const int bid  = blockIdx.x;
    const int lane = tid & 31;
    const int w    = tid >> 5;
    unsigned nbar = 0;
    __shared__ float sred[256];

    int gi = bid * 256 + tid;
    if (gi < N) { g_u[gi] = 1.0f; g_v[gi] = 1.0f; }
    gsync(&nbar);

    for (int it = 0; it < ITERS; it++) {
        // ---- u-pass: warp-per-row, skip all-zero tiles ----
#pragma unroll
        for (int rr = 0; rr < 4; rr++) {
            int r  = bid * 32 + w * 4 + rr;
            int rt = r >> 7;
            const int* map = g_tilemap + rt * NT;
            const float4* kr = (const float4*)(g_K + (size_t)r * N);
            const float4* vv = (const float4*)g_v;
            float s = 0.0f;
            for (int ct = 0; ct < NT; ct++) {
                if (!map[ct]) continue;
                int j = ct * 32 + lane;   // float4 index within row
                float4 kq = kr[j];
                float4 vq = vv[j];
                s += kq.x * vq.x + kq.y * vq.y + kq.z * vq.z + kq.w * vq.w;
            }
#pragma unroll
            for (int o = 16; o; o >>= 1) s += __shfl_xor_sync(0xffffffffu, s, o);
            if (lane == 0) {
                float un = AB / (s + DELTA);
                if (un != g_u[r]) g_changed[it] = 1;
                g_u[r] = un;
            }
        }
        gsync(&nbar);

        // ---- v-pass: 32-col stripe per block, skip all-zero tiles ----
        {
            int c  = bid * 32 + lane;
            int ct = bid >> 2;
            float s = 0.0f;
            for (int rt = 0; rt < NT; rt++) {
                if (!g_tilemap[rt * NT + ct]) continue;
                int rbase = rt * 128;
#pragma unroll 4
                for (int r = rbase + w; r < rbase + 128; r += 8)
                    s += g_K[(size_t)r * N + c] * g_u[r];
            }
            sred[tid] = s;
            __syncthreads();
            if (tid < 32) {
                float t = sred[tid];
#pragma unroll
                for (int g = 1; g < 8; g++) t += sred[tid + g * 32];
                float vn = AB / (t + DELTA);
                if (vn != g_v[c]) g_changed[it] = 1;
                g_v[c] = vn;
            }
        }
        gsync(&nbar);

        if (g_changed[it] == 0) break;   // exact bitwise fixed point
    }

    // ---- cost = sum_ij u_i * K_ij * v_j * M_ij (zero tiles contribute 0) ----
    {
        float wsum = 0.0f;
#pragma unroll
        for (int rr = 0; rr < 4; rr++) {
            int r  = bid * 32 + w * 4 + rr;
            int rt = r >> 7;
            const int* map = g_tilemap + rt * NT;
            const float4* kr = (const float4*)(g_K + (size_t)r * N);
            const float4* mr = (const float4*)(g_M + (size_t)r * N);
            const float4* vv = (const float4*)g_v;
            float s = 0.0f;
            for (int ct = 0; ct < NT; ct++) {
                if (!map[ct]) continue;
                int j = ct * 32 + lane;
                float4 kq = kr[j];
                float4 mq = mr[j];
                float4 vq = vv[j];
                s += kq.x * mq.x * vq.x + kq.y * mq.y * vq.y
                   + kq.z * mq.z * vq.z + kq.w * mq.w * vq.w;
            }
#pragma unroll
            for (int o = 16; o; o >>= 1) s += __shfl_xor_sync(0xffffffffu, s, o);
            if (lane == 0) wsum += s * g_u[r];
        }
        if (lane == 0) atomicAdd(&g_cost, wsum);
    }
    gsync(&nbar);
    if (bid == 0 && tid == 0) out[0] = g_cost;
}

// ---------------- launch ----------------------------------------------------------
extern "C" void kernel_launch(void* const* d_in, const int* in_sizes, int n_in,
                              void* d_out, int out_size) {
    const float* x0 = (const float*)d_in[0];
    const float* x1 = (const float*)d_in[1];
    float* out = (float*)d_out;

    kern_norms<<<32, 256>>>(x0, x1);          // fused init + norms + bf16 convert
    dim3 gk(NT, NT);
    kern_K<<<gk, 256>>>();
    kern_sinkhorn<<<NB, 256>>>(out);
}

// round 6
// speedup vs baseline: 15.1050x; 1.8630x over previous
#include <cuda_runtime.h>
#include <cuda_bf16.h>
#include <cstdint>

#define N      4096
#define D      64
#define NB     128      // persistent-kernel block count (<= SMs => co-resident)
#define ITERS  100
#define NT     32       // 32x32 grid of 128x128 tiles

// ---------------- device globals (scratch; no allocation allowed) ----------------
__device__ float    g_K[(size_t)N * N];   // written only for nonzero tiles
__device__ float    g_M[(size_t)N * N];   // written only for nonzero tiles
__device__ float    g_u[N];
__device__ float    g_v[N];
__device__ unsigned g_arrive;
__device__ int      g_changed[ITERS];
__device__ float    g_cost;
__device__ int      g_tilemap[NT * NT];   // written by EVERY kern_K block (0 or 1)

// ---------------- fused K/M build: fp32 loads + in-pass norms + bf16 mma ----------
// Block = 256 threads = 8 warps (2 m-groups x 4 n-groups). Tile 128x128, K=64.
// smem row stride = 36 uint32 (144 B): bank(r*36+c) = (r*4+c) % 32 -> the mma
// fragment read pattern (gid,pid) hits all 32 banks; 144 % 8 == 0 keeps uint2 ok.
#define SROW 36
__global__ void __launch_bounds__(256) kern_K(const float* __restrict__ x0,
                                              const float* __restrict__ x1) {
    __shared__ uint32_t As[128 * SROW];
    __shared__ uint32_t Bs[128 * SROW];
    __shared__ float    sqA[128], sqB[128];

    const int tid  = threadIdx.x;
    const int w    = tid >> 5;
    const int lane = tid & 31;
    const int gid  = lane >> 2;     // 0..7
    const int pid  = lane & 3;      // 0..3
    const int wm   = w >> 2;        // 0..1
    const int wn   = w & 3;         // 0..3
    const int R0 = blockIdx.y * 128;
    const int C0 = blockIdx.x * 128;

    // Per-launch state reset (block (0,0) only; sinkhorn launches after boundary)
    if (blockIdx.x == 0 && blockIdx.y == 0) {
        if (tid == 0) { g_arrive = 0u; g_cost = 0.0f; }
        if (tid < ITERS) g_changed[tid] = 0;
    }

    // ---- coalesced fp32 tile loads + bf16 convert + in-pass row norms ----
    // 128 rows x 16 float4 per operand; 8 iterations x 256 threads.
    // Each row is covered by 16 consecutive lanes in one iteration -> full
    // row norm via a 16-lane shfl tree.
    const float* GA = x0 + (size_t)R0 * D;
    const float* GB = x1 + (size_t)C0 * D;
#pragma unroll
    for (int i = 0; i < 8; i++) {
        int f  = tid + i * 256;      // 0..2047
        int r  = f >> 4;             // local row
        int c4 = f & 15;             // float4 within row
        float4 qa = *(const float4*)(GA + (size_t)r * D + c4 * 4);
        float4 qb = *(const float4*)(GB + (size_t)r * D + c4 * 4);

        __nv_bfloat162 a0 = __floats2bfloat162_rn(qa.x, qa.y);
        __nv_bfloat162 a1 = __floats2bfloat162_rn(qa.z, qa.w);
        __nv_bfloat162 b0 = __floats2bfloat162_rn(qb.x, qb.y);
        __nv_bfloat162 b1 = __floats2bfloat162_rn(qb.z, qb.w);
        As[r * SROW + c4 * 2]     = *(uint32_t*)&a0;
        As[r * SROW + c4 * 2 + 1] = *(uint32_t*)&a1;
        Bs[r * SROW + c4 * 2]     = *(uint32_t*)&b0;
        Bs[r * SROW + c4 * 2 + 1] = *(uint32_t*)&b1;

        float sa = qa.x * qa.x + qa.y * qa.y + qa.z * qa.z + qa.w * qa.w;
        float sb = qb.x * qb.x + qb.y * qb.y + qb.z * qb.z + qb.w * qb.w;
#pragma unroll
        for (int o = 8; o; o >>= 1) {
            sa += __shfl_xor_sync(0xffffffffu, sa, o);
            sb += __shfl_xor_sync(0xffffffffu, sb, o);
        }
        if (c4 == 0) { sqA[r] = sa; sqB[r] = sb; }
    }
    __syncthreads();

    const int AR = wm * 64;          // warp's local A row base
    const int BR = wn * 32;          // warp's local B row base

    float acc[4][4][4];
#pragma unroll
    for (int mi = 0; mi < 4; mi++)
#pragma unroll
        for (int ni = 0; ni < 4; ni++)
#pragma unroll
            for (int f = 0; f < 4; f++) acc[mi][ni][f] = 0.0f;

#pragma unroll
    for (int ks = 0; ks < 4; ks++) {
        const int cidx = ks * 8 + pid;   // uint32 col (k/2)
        uint32_t a[4][4];
#pragma unroll
        for (int mi = 0; mi < 4; mi++) {
            int r = AR + mi * 16 + gid;
            a[mi][0] = As[r * SROW + cidx];
            a[mi][1] = As[(r + 8) * SROW + cidx];
            a[mi][2] = As[r * SROW + cidx + 4];
            a[mi][3] = As[(r + 8) * SROW + cidx + 4];
        }
        uint32_t b[4][2];
#pragma unroll
        for (int ni = 0; ni < 4; ni++) {
            int c = BR + ni * 8 + gid;
            b[ni][0] = Bs[c * SROW + cidx];
            b[ni][1] = Bs[c * SROW + cidx + 4];
        }
#pragma unroll
        for (int mi = 0; mi < 4; mi++)
#pragma unroll
            for (int ni = 0; ni < 4; ni++)
                asm volatile(
                    "mma.sync.aligned.m16n8k16.row.col.f32.bf16.bf16.f32 "
                    "{%0,%1,%2,%3}, {%4,%5,%6,%7}, {%8,%9}, {%0,%1,%2,%3};"
                    : "+f"(acc[mi][ni][0]), "+f"(acc[mi][ni][1]),
                      "+f"(acc[mi][ni][2]), "+f"(acc[mi][ni][3])
                    : "r"(a[mi][0]), "r"(a[mi][1]), "r"(a[mi][2]), "r"(a[mi][3]),
                      "r"(b[ni][0]), "r"(b[ni][1]));
    }

    // Epilogue: m = max(sq0+sq1-2dot, 0). Tile materialized only if some element
    // could have exp(-m/0.1) != 0 in fp32 (m < ~10.4; margin 11 covers bf16 error).
    __shared__ int s_need;
    if (tid == 0) s_need = 0;
    __syncthreads();

    const int LR0 = wm * 64;         // local warp row base within tile
    const int LC0 = wn * 32;
    float mv[4][4][4];
    int need = 0;
#pragma unroll
    for (int mi = 0; mi < 4; mi++) {
        float s0a = sqA[LR0 + mi * 16 + gid];
        float s0b = sqA[LR0 + mi * 16 + gid + 8];
#pragma unroll
        for (int ni = 0; ni < 4; ni++) {
            int lc = LC0 + ni * 8 + 2 * pid;
            float s1a = sqB[lc], s1b = sqB[lc + 1];
            float m0 = fmaxf(fmaf(-2.0f, acc[mi][ni][0], s0a + s1a), 0.0f);
            float m1 = fmaxf(fmaf(-2.0f, acc[mi][ni][1], s0a + s1b), 0.0f);
            float m2 = fmaxf(fmaf(-2.0f, acc[mi][ni][2], s0b + s1a), 0.0f);
            float m3 = fmaxf(fmaf(-2.0f, acc[mi][ni][3], s0b + s1b), 0.0f);
            mv[mi][ni][0] = m0; mv[mi][ni][1] = m1;
            mv[mi][ni][2] = m2; mv[mi][ni][3] = m3;
            need |= (fminf(fminf(m0, m1), fminf(m2, m3)) < 11.0f) ? 1 : 0;
        }
    }
    unsigned wb = __ballot_sync(0xffffffffu, need);
    if (lane == 0 && wb) s_need = 1;
    __syncthreads();

    if (tid == 0) g_tilemap[blockIdx.y * NT + blockIdx.x] = s_need;

    if (s_need) {
#pragma unroll
        for (int mi = 0; mi < 4; mi++) {
#pragma unroll
            for (int ni = 0; ni < 4; ni++) {
                int r0 = R0 + LR0 + mi * 16 + gid;
                int c  = C0 + LC0 + ni * 8 + 2 * pid;
                float m0 = mv[mi][ni][0], m1 = mv[mi][ni][1];
                float m2 = mv[mi][ni][2], m3 = mv[mi][ni][3];
                *(float2*)(g_M + (size_t)r0 * N + c)       = make_float2(m0, m1);
                *(float2*)(g_M + (size_t)(r0 + 8) * N + c) = make_float2(m2, m3);
                *(float2*)(g_K + (size_t)r0 * N + c)       =
                    make_float2(expf(-10.0f * m0), expf(-10.0f * m1));
                *(float2*)(g_K + (size_t)(r0 + 8) * N + c) =
                    make_float2(expf(-10.0f * m2), expf(-10.0f * m3));
            }
        }
    }
}

// ---------------- software grid barrier -------------------------------------------
__device__ __forceinline__ void gsync(unsigned* nbar) {
    __syncthreads();
    if (threadIdx.x == 0) {
        __threadfence();
        atomicAdd(&g_arrive, 1u);
        unsigned tgt = (*nbar + 1u) * (unsigned)NB;
        while (atomicAdd(&g_arrive, 0u) < tgt) __nanosleep(64);
        __threadfence();
    }
    (*nbar)++;
    __syncthreads();
}

// ---------------- persistent Sinkhorn + cost --------------------------------------
__global__ void __launch_bounds__(256) kern_sinkhorn(float* __restrict__ out) {
    const int tid  = threadIdx.x;
    const int bid  = blockIdx.x;

    // Exact fast path: if every tile of K is identically zero, then K@v == 0,
    // K^T@u == 0, and every cost term u_i*K_ij*v_j*M_ij == 0 -> cost == 0.
    {
        int loc = 0;
#pragma unroll
        for (int t = tid; t < NT * NT; t += 256) loc |= g_tilemap[t];
        if (!__syncthreads_or(loc)) {
            if (bid == 0 && tid == 0) out[0] = 0.0f;
            return;
        }
    }

    const float AB    = 1.0f / (float)N;
    const float DELTA = 1e-8f;
    const int lane = tid & 31;
    const int w    = tid >> 5;
    unsigned nbar = 0;
    __shared__ float sred[256];

    int gi = bid * 256 + tid;
    if (gi < N) { g_u[gi] = 1.0f; g_v[gi] = 1.0f; }
    gsync(&nbar);

    for (int it = 0; it < ITERS; it++) {
        // ---- u-pass: warp-per-row, skip all-zero tiles ----
#pragma unroll
        for (int rr = 0; rr < 4; rr++) {
            int r  = bid * 32 + w * 4 + rr;
            int rt = r >> 7;
            const int* map = g_tilemap + rt * NT;
            const float4* kr = (const float4*)(g_K + (size_t)r * N);
            const float4* vv = (const float4*)g_v;
            float s = 0.0f;
            for (int ct = 0; ct < NT; ct++) {
                if (!map[ct]) continue;
                int j = ct * 32 + lane;   // float4 index within row
                float4 kq = kr[j];
                float4 vq = vv[j];
                s += kq.x * vq.x + kq.y * vq.y + kq.z * vq.z + kq.w * vq.w;
            }
#pragma unroll
            for (int o = 16; o; o >>= 1) s += __shfl_xor_sync(0xffffffffu, s, o);
            if (lane == 0) {
                float un = AB / (s + DELTA);
                if (un != g_u[r]) g_changed[it] = 1;
                g_u[r] = un;
            }
        }
        gsync(&nbar);

        // ---- v-pass: 32-col stripe per block, skip all-zero tiles ----
        {
            int c  = bid * 32 + lane;
            int ct = bid >> 2;
            float s = 0.0f;
            for (int rt = 0; rt < NT; rt++) {
                if (!g_tilemap[rt * NT + ct]) continue;
                int rbase = rt * 128;
#pragma unroll 4
                for (int r = rbase + w; r < rbase + 128; r += 8)
                    s += g_K[(size_t)r * N + c] * g_u[r];
            }
            sred[tid] = s;
            __syncthreads();
            if (tid < 32) {
                float t = sred[tid];
#pragma unroll
                for (int g = 1; g < 8; g++) t += sred[tid + g * 32];
                float vn = AB / (t + DELTA);
                if (vn != g_v[c]) g_changed[it] = 1;
                g_v[c] = vn;
            }
        }
        gsync(&nbar);

        if (g_changed[it] == 0) break;   // exact bitwise fixed point
    }

    // ---- cost = sum_ij u_i * K_ij * v_j * M_ij (zero tiles contribute 0) ----
    {
        float wsum = 0.0f;
#pragma unroll
        for (int rr = 0; rr < 4; rr++) {
            int r  = bid * 32 + w * 4 + rr;
            int rt = r >> 7;
            const int* map = g_tilemap + rt * NT;
            const float4* kr = (const float4*)(g_K + (size_t)r * N);
            const float4* mr = (const float4*)(g_M + (size_t)r * N);
            const float4* vv = (const float4*)g_v;
            float s = 0.0f;
            for (int ct = 0; ct < NT; ct++) {
                if (!map[ct]) continue;
                int j = ct * 32 + lane;
                float4 kq = kr[j];
                float4 mq = mr[j];
                float4 vq = vv[j];
                s += kq.x * mq.x * vq.x + kq.y * mq.y * vq.y
                   + kq.z * mq.z * vq.z + kq.w * mq.w * vq.w;
            }
#pragma unroll
            for (int o = 16; o; o >>= 1) s += __shfl_xor_sync(0xffffffffu, s, o);
            if (lane == 0) wsum += s * g_u[r];
        }
        if (lane == 0) atomicAdd(&g_cost, wsum);
    }
    gsync(&nbar);
    if (bid == 0 && tid == 0) out[0] = g_cost;
}

// ---------------- launch ----------------------------------------------------------
extern "C" void kernel_launch(void* const* d_in, const int* in_sizes, int n_in,
                              void* d_out, int out_size) {
    const float* x0 = (const float*)d_in[0];
    const float* x1 = (const float*)d_in[1];
    float* out = (float*)d_out;

    dim3 gk(NT, NT);
    kern_K<<<gk, 256>>>(x0, x1);
    kern_sinkhorn<<<NB, 256>>>(out);
}